// round 7
// baseline (speedup 1.0000x reference)
#include <cuda_runtime.h>
#include <cuda_bf16.h>
#include <cstdint>

#define THREADS 512
#define TILE_E  64              // M per CTA
#define KTOT    896
#define HTOT    384
#define NCH     14              // 896/64
#define NWARP_N 8               // warps along N
#define NB_PER_W 6              // nb slots per warp: 1 structural + 3 chemical + 2 combined

// ---------- packed weights (built per launch) ----------
// Fragment-order bf16: index = (((c*48 + nb)*4 + ks)*32 + lane)*4 + reg*2 + pair
__device__ __align__(16) __nv_bfloat16 g_Bp_hi[KTOT * HTOT];
__device__ __align__(16) __nv_bfloat16 g_Bp_lo[KTOT * HTOT];
__device__ float g_b1[HTOT];
__device__ float g_w2[HTOT];

__global__ void pack_kernel(
    const float* __restrict__ sw1, const float* __restrict__ sb1, const float* __restrict__ sw2,
    const float* __restrict__ cw1, const float* __restrict__ cb1, const float* __restrict__ cw2,
    const float* __restrict__ mw1, const float* __restrict__ mb1, const float* __restrict__ mw2)
{
    int idx = blockIdx.x * blockDim.x + threadIdx.x;
    if (idx < KTOT * HTOT) {
        int k = idx / HTOT;
        int j = idx - k * HTOT;
        float v = 0.f;
        if (j < 64) {
            if (k < 128) v = sw1[k * 64 + j];
        } else if (j < 256) {
            if (k >= 128) v = cw1[(k - 128) * 192 + (j - 64)];
        } else {
            v = mw1[k * 128 + (j - 256)];
        }
        __nv_bfloat16 vh = __float2bfloat16(v);
        __nv_bfloat16 vl = __float2bfloat16(v - __bfloat162float(vh));
        int c  = k >> 6;
        int kk = k & 63;
        int ks = kk >> 4;
        int kr = kk & 15;
        int nb = j >> 3;
        int nr = j & 7;
        int lane = nr * 4 + ((kr & 7) >> 1);
        int reg  = kr >> 3;
        int pair = kr & 1;
        uint32_t off = ((((uint32_t)(c * 48 + nb) * 4 + ks) * 32 + lane) * 4) + reg * 2 + pair;
        g_Bp_hi[off] = vh;
        g_Bp_lo[off] = vl;
    } else if (idx < KTOT * HTOT + HTOT) {
        int j = idx - KTOT * HTOT;
        float b, w;
        if (j < 64)       { b = sb1[j];       w = sw2[j]; }
        else if (j < 256) { b = cb1[j - 64];  w = cw2[j - 64]; }
        else              { b = mb1[j - 256]; w = mw2[j - 256]; }
        g_b1[j] = b;
        g_w2[j] = w;
    }
}

__device__ __forceinline__ void mma16816(float* d, const uint32_t* a, const uint32_t b0, const uint32_t b1) {
    asm volatile(
        "mma.sync.aligned.m16n8k16.row.col.f32.bf16.bf16.f32 "
        "{%0,%1,%2,%3}, {%4,%5,%6,%7}, {%8,%9}, {%0,%1,%2,%3};"
        : "+f"(d[0]), "+f"(d[1]), "+f"(d[2]), "+f"(d[3])
        : "r"(a[0]), "r"(a[1]), "r"(a[2]), "r"(a[3]), "r"(b0), "r"(b1));
}

__device__ __forceinline__ uint32_t pack_bf16x2(float x, float y) {
    __nv_bfloat162 h = __floats2bfloat162_rn(x, y);
    return *reinterpret_cast<uint32_t*>(&h);
}

#define ABLK 528
#define AREG (16 * ABLK)

// MMA block over a static slot list. term-outer ordering => consecutive MMAs
// hit different accumulators (dep distance >= 2*NACT).
#define MMA_CHUNK(NACT, ...)                                                      \
    {                                                                             \
        const int slist[NACT] = __VA_ARGS__;                                      \
        _Pragma("unroll")                                                         \
        for (int ks = 0; ks < 4; ks++) {                                          \
            uint32_t afh[2][4], afl[2][4];                                        \
            _Pragma("unroll")                                                     \
            for (int f = 0; f < 2; f++) {                                         \
                uint32_t boff = (uint32_t)((mw * 2 + f) * 4 + ks) * ABLK + lane * 16; \
                uint4 vh = *(const uint4*)(ah + boff);                            \
                uint4 vl = *(const uint4*)(al + boff);                            \
                afh[f][0] = vh.x; afh[f][1] = vh.y; afh[f][2] = vh.z; afh[f][3] = vh.w; \
                afl[f][0] = vl.x; afl[f][1] = vl.y; afl[f][2] = vl.z; afl[f][3] = vl.w; \
            }                                                                     \
            uint2 bh[NACT], bl[NACT];                                             \
            _Pragma("unroll")                                                     \
            for (int i = 0; i < NACT; i++) {                                      \
                uint32_t bidx = (((uint32_t)(c * 48 + nbg[slist[i]]) * 4 + ks) * 32 + lane); \
                bh[i] = Bhi[bidx];                                                \
                bl[i] = Blo[bidx];                                                \
            }                                                                     \
            _Pragma("unroll")                                                     \
            for (int i = 0; i < NACT; i++)                                        \
                _Pragma("unroll")                                                 \
                for (int f = 0; f < 2; f++)                                       \
                    mma16816(acc[f][slist[i]], afh[f], bh[i].x, bh[i].y);         \
            _Pragma("unroll")                                                     \
            for (int i = 0; i < NACT; i++)                                        \
                _Pragma("unroll")                                                 \
                for (int f = 0; f < 2; f++)                                       \
                    mma16816(acc[f][slist[i]], afh[f], bl[i].x, bl[i].y);         \
            _Pragma("unroll")                                                     \
            for (int i = 0; i < NACT; i++)                                        \
                _Pragma("unroll")                                                 \
                for (int f = 0; f < 2; f++)                                       \
                    mma16816(acc[f][slist[i]], afl[f], bh[i].x, bh[i].y);         \
        }                                                                         \
    }

__global__ void __launch_bounds__(THREADS, 1)
decoder_kernel(
    const float* __restrict__ z, const float* __restrict__ chem,
    const int*   __restrict__ edge, const int* __restrict__ mask,
    const float* __restrict__ sb2, const float* __restrict__ cb2,
    const float* __restrict__ mb2, const float* __restrict__ pw,
    float* __restrict__ out, int E)
{
    __shared__ __align__(16) char Asm[2][2][AREG];
    __shared__ float red[NWARP_N][3][TILE_E];
    __shared__ int   Ssrc[TILE_E], Sdst[TILE_E];
    __shared__ float Sbv[TILE_E];

    const int tid  = threadIdx.x;
    const int wid  = tid >> 5;
    const int lane = tid & 31;
    const int nw   = wid & 7;
    const int mw   = wid >> 3;
    const int ebase = blockIdx.x * TILE_E;

    // slot -> global nb: slot0 structural, slots1-3 chemical, slots4-5 combined
    const int nbg[NB_PER_W] = { nw, 8 + nw * 3, 9 + nw * 3, 10 + nw * 3,
                                32 + nw * 2, 33 + nw * 2 };

    if (tid < TILE_E) {
        int ge = ebase + tid;
        int s = 0, d = 0;
        float bv = 0.f;
        if (ge < E) {
            s  = edge[2 * ge + 0];
            d  = edge[2 * ge + 1];
            bv = (float)(mask[s] * mask[d]);
        }
        Ssrc[tid] = s; Sdst[tid] = d; Sbv[tid] = bv;
    }
    for (int i = tid; i < NWARP_N * 3 * TILE_E; i += THREADS)
        ((float*)red)[i] = 0.f;
    __syncthreads();

    // gather mapping: e = tid/8, q = tid%8 (8-k slice = 2 float4)
    const int ge_ = tid >> 3;
    const int q   = tid & 7;
    const int r   = ge_ & 15;
    const int fm  = ge_ >> 4;
    const uint32_t abase = (uint32_t)(fm * 4 + (q >> 1)) * ABLK
                         + (uint32_t)((r & 7) * 64 + (r >> 3) * 4 + (q & 1) * 8);
    const int srow = Ssrc[ge_];
    const int drow = Sdst[ge_];

    float4 ga[2], gb[2];
    {
        const float* sp = z + (size_t)srow * 128 + q * 8;
        const float* dp = z + (size_t)drow * 128 + q * 8;
        ga[0] = *(const float4*)(sp);     ga[1] = *(const float4*)(sp + 4);
        gb[0] = *(const float4*)(dp);     gb[1] = *(const float4*)(dp + 4);
    }

    float acc[2][NB_PER_W][4];
    #pragma unroll
    for (int a = 0; a < 2; a++)
        #pragma unroll
        for (int b = 0; b < NB_PER_W; b++)
            #pragma unroll
            for (int qq = 0; qq < 4; qq++) acc[a][b][qq] = 0.f;

    const uint2* __restrict__ Bhi = (const uint2*)g_Bp_hi;
    const uint2* __restrict__ Blo = (const uint2*)g_Bp_lo;

    #pragma unroll 1
    for (int c = 0; c < NCH; c++) {
        // ---- stage chunk c ----
        {
            char* sah = Asm[c & 1][0];
            char* sal = Asm[c & 1][1];
            #pragma unroll
            for (int i = 0; i < 2; i++) {
                float p0 = ga[i].x * gb[i].x;
                float p1 = ga[i].y * gb[i].y;
                float p2 = ga[i].z * gb[i].z;
                float p3 = ga[i].w * gb[i].w;
                __nv_bfloat16 h0 = __float2bfloat16(p0), h1 = __float2bfloat16(p1);
                __nv_bfloat16 h2 = __float2bfloat16(p2), h3 = __float2bfloat16(p3);
                float l0 = p0 - __bfloat162float(h0);
                float l1 = p1 - __bfloat162float(h1);
                float l2 = p2 - __bfloat162float(h2);
                float l3 = p3 - __bfloat162float(h3);
                uint32_t hi01 = ((uint32_t)__bfloat16_as_ushort(h0)) | ((uint32_t)__bfloat16_as_ushort(h1) << 16);
                uint32_t hi23 = ((uint32_t)__bfloat16_as_ushort(h2)) | ((uint32_t)__bfloat16_as_ushort(h3) << 16);
                uint32_t lo01 = pack_bf16x2(l0, l1);
                uint32_t lo23 = pack_bf16x2(l2, l3);
                uint32_t a0 = abase + (uint32_t)(i * 32);
                uint32_t a1 = a0 + 16;
                *(uint32_t*)(sah + a0) = hi01;
                *(uint32_t*)(sah + a1) = hi23;
                *(uint32_t*)(sal + a0) = lo01;
                *(uint32_t*)(sal + a1) = lo23;
            }
        }
        __syncthreads();

        // ---- prefetch gather for chunk c+1 ----
        if (c + 1 < NCH) {
            int cn = c + 1;
            const float* basep = (cn < 2) ? z : chem;
            int ldr = (cn < 2) ? 128 : 768;
            int kb  = (cn < 2) ? cn * 64 : (cn - 2) * 64;
            const float* sp = basep + (size_t)srow * ldr + kb + q * 8;
            const float* dp = basep + (size_t)drow * ldr + kb + q * 8;
            ga[0] = *(const float4*)(sp);     ga[1] = *(const float4*)(sp + 4);
            gb[0] = *(const float4*)(dp);     gb[1] = *(const float4*)(dp + 4);
        }

        // ---- MMA: only non-zero weight blocks ----
        {
            const char* ah = Asm[c & 1][0];
            const char* al = Asm[c & 1][1];
            if (c < 2) {
                MMA_CHUNK(3, { 0, 4, 5 })          // structural + combined cols
            } else {
                MMA_CHUNK(5, { 1, 2, 3, 4, 5 })    // chemical + combined cols
            }
        }
    }
    __syncthreads();

    // ---- epilogue ----
    {
        const int qc = (lane & 3) * 2;
        float ps[4][3];
        #pragma unroll
        for (int s = 0; s < 4; s++)
            #pragma unroll
            for (int p = 0; p < 3; p++) ps[s][p] = 0.f;

        #pragma unroll
        for (int sl = 0; sl < NB_PER_W; sl++) {
            int col0 = nbg[sl] * 8;
            int p = (sl == 0) ? 0 : (sl < 4) ? 1 : 2;
            float bb0 = g_b1[col0 + qc],     bb1 = g_b1[col0 + qc + 1];
            float ww0 = g_w2[col0 + qc],     ww1 = g_w2[col0 + qc + 1];
            #pragma unroll
            for (int f = 0; f < 2; f++) {
                const float* a = acc[f][sl];
                ps[f * 2 + 0][p] += fmaxf(a[0] + bb0, 0.f) * ww0 + fmaxf(a[1] + bb1, 0.f) * ww1;
                ps[f * 2 + 1][p] += fmaxf(a[2] + bb0, 0.f) * ww0 + fmaxf(a[3] + bb1, 0.f) * ww1;
            }
        }
        #pragma unroll
        for (int s = 0; s < 4; s++)
            #pragma unroll
            for (int p = 0; p < 3; p++) {
                float v = ps[s][p];
                v += __shfl_xor_sync(0xffffffffu, v, 1);
                v += __shfl_xor_sync(0xffffffffu, v, 2);
                ps[s][p] = v;
            }
        if ((lane & 3) == 0) {
            #pragma unroll
            for (int f = 0; f < 2; f++)
                #pragma unroll
                for (int rr = 0; rr < 2; rr++) {
                    int el = (mw * 2 + f) * 16 + (lane >> 2) + rr * 8;
                    #pragma unroll
                    for (int p = 0; p < 3; p++)
                        red[nw][p][el] += ps[f * 2 + rr][p];
                }
        }
    }
    __syncthreads();

    if (tid < TILE_E && ebase + tid < E) {
        float s0 = 0.f, s1 = 0.f, s2 = 0.f;
        #pragma unroll
        for (int w = 0; w < NWARP_N; w++) {
            s0 += red[w][0][tid];
            s1 += red[w][1][tid];
            s2 += red[w][2][tid];
        }
        float p0 = pw[0], p1 = pw[1], p2 = pw[2];
        float mx = fmaxf(p0, fmaxf(p1, p2));
        float e0 = expf(p0 - mx), e1 = expf(p1 - mx), e2 = expf(p2 - mx);
        float inv = 1.f / (e0 + e1 + e2);
        float ss = s0 + sb2[0];
        float sc = s1 + cb2[0];
        float sm = s2 + mb2[0];
        float comb = (e0 * ss + e1 * sc + e2 * sm) * inv;
        out[ebase + tid] = (Sbv[tid] > 0.5f) ? comb : ss;
    }
}

extern "C" void kernel_launch(void* const* d_in, const int* in_sizes, int n_in,
                              void* d_out, int out_size)
{
    const float* z    = (const float*)d_in[0];
    const float* chem = (const float*)d_in[1];
    const int*   edge = (const int*)d_in[2];
    const int*   mask = (const int*)d_in[3];
    const float* sw1  = (const float*)d_in[4];
    const float* sb1  = (const float*)d_in[5];
    const float* sw2  = (const float*)d_in[6];
    const float* sb2  = (const float*)d_in[7];
    const float* cw1  = (const float*)d_in[8];
    const float* cb1  = (const float*)d_in[9];
    const float* cw2  = (const float*)d_in[10];
    const float* cb2  = (const float*)d_in[11];
    const float* mw1  = (const float*)d_in[12];
    const float* mb1  = (const float*)d_in[13];
    const float* mw2  = (const float*)d_in[14];
    const float* mb2  = (const float*)d_in[15];
    const float* pw   = (const float*)d_in[16];
    float*       out  = (float*)d_out;

    const int E = in_sizes[2] / 2;

    {
        int total = KTOT * HTOT + HTOT;
        pack_kernel<<<(total + 255) / 256, 256>>>(sw1, sb1, sw2,
                                                  cw1, cb1, cw2,
                                                  mw1, mb1, mw2);
    }

    const int nblocks = (E + TILE_E - 1) / TILE_E;
    decoder_kernel<<<nblocks, THREADS>>>(
        z, chem, edge, mask, sb2, cb2, mb2, pw, out, E);
}

// round 9
// speedup vs baseline: 1.4826x; 1.4826x over previous
#include <cuda_runtime.h>
#include <cuda_bf16.h>
#include <cstdint>

#define THREADS 512
#define TILE_E  64              // M per CTA
#define KTOT    896
#define HTOT    384
#define NCH     14              // 896/64
#define NWARP_N 8               // warps along N
#define NB_PER_W 6              // nb slots per warp: 1 structural + 3 chemical + 2 combined

// ---------- packed weights (built per launch) ----------
// Fragment-order bf16: index = (((c*48 + nb)*4 + ks)*32 + lane)*4 + reg*2 + pair
__device__ __align__(16) __nv_bfloat16 g_Bp_hi[KTOT * HTOT];
__device__ __align__(16) __nv_bfloat16 g_Bp_lo[KTOT * HTOT];
__device__ float g_b1[HTOT];
__device__ float g_w2[HTOT];

__global__ void pack_kernel(
    const float* __restrict__ sw1, const float* __restrict__ sb1, const float* __restrict__ sw2,
    const float* __restrict__ cw1, const float* __restrict__ cb1, const float* __restrict__ cw2,
    const float* __restrict__ mw1, const float* __restrict__ mb1, const float* __restrict__ mw2)
{
    int idx = blockIdx.x * blockDim.x + threadIdx.x;
    if (idx < KTOT * HTOT) {
        int k = idx / HTOT;
        int j = idx - k * HTOT;
        float v = 0.f;
        if (j < 64) {
            if (k < 128) v = sw1[k * 64 + j];
        } else if (j < 256) {
            if (k >= 128) v = cw1[(k - 128) * 192 + (j - 64)];
        } else {
            v = mw1[k * 128 + (j - 256)];
        }
        __nv_bfloat16 vh = __float2bfloat16(v);
        __nv_bfloat16 vl = __float2bfloat16(v - __bfloat162float(vh));
        int c  = k >> 6;
        int kk = k & 63;
        int ks = kk >> 4;
        int kr = kk & 15;
        int nb = j >> 3;
        int nr = j & 7;
        int lane = nr * 4 + ((kr & 7) >> 1);
        int reg  = kr >> 3;
        int pair = kr & 1;
        uint32_t off = ((((uint32_t)(c * 48 + nb) * 4 + ks) * 32 + lane) * 4) + reg * 2 + pair;
        g_Bp_hi[off] = vh;
        g_Bp_lo[off] = vl;
    } else if (idx < KTOT * HTOT + HTOT) {
        int j = idx - KTOT * HTOT;
        float b, w;
        if (j < 64)       { b = sb1[j];       w = sw2[j]; }
        else if (j < 256) { b = cb1[j - 64];  w = cw2[j - 64]; }
        else              { b = mb1[j - 256]; w = mw2[j - 256]; }
        g_b1[j] = b;
        g_w2[j] = w;
    }
}

__device__ __forceinline__ void mma16816(float* d, const uint32_t* a, const uint32_t b0, const uint32_t b1) {
    asm volatile(
        "mma.sync.aligned.m16n8k16.row.col.f32.bf16.bf16.f32 "
        "{%0,%1,%2,%3}, {%4,%5,%6,%7}, {%8,%9}, {%0,%1,%2,%3};"
        : "+f"(d[0]), "+f"(d[1]), "+f"(d[2]), "+f"(d[3])
        : "r"(a[0]), "r"(a[1]), "r"(a[2]), "r"(a[3]), "r"(b0), "r"(b1));
}

__device__ __forceinline__ uint32_t pack_bf16x2(float x, float y) {
    __nv_bfloat162 h = __floats2bfloat162_rn(x, y);
    return *reinterpret_cast<uint32_t*>(&h);
}

#define ABLK 528
#define AREG (16 * ABLK)

// Round-6 MMA body (slot-outer, B just-in-time, one bh/bl pair live at a time),
// restricted to a compile-time active-slot list.
#define MMA_CHUNK(NACT, ...)                                                      \
    {                                                                             \
        const int slist[NACT] = __VA_ARGS__;                                      \
        _Pragma("unroll")                                                         \
        for (int ks = 0; ks < 4; ks++) {                                          \
            uint32_t afh[2][4], afl[2][4];                                        \
            _Pragma("unroll")                                                     \
            for (int f = 0; f < 2; f++) {                                         \
                uint32_t boff = (uint32_t)((mw * 2 + f) * 4 + ks) * ABLK + lane * 16; \
                uint4 vh = *(const uint4*)(ah + boff);                            \
                uint4 vl = *(const uint4*)(al + boff);                            \
                afh[f][0] = vh.x; afh[f][1] = vh.y; afh[f][2] = vh.z; afh[f][3] = vh.w; \
                afl[f][0] = vl.x; afl[f][1] = vl.y; afl[f][2] = vl.z; afl[f][3] = vl.w; \
            }                                                                     \
            _Pragma("unroll")                                                     \
            for (int i = 0; i < NACT; i++) {                                      \
                const int sl = slist[i];                                          \
                uint32_t bidx = (((uint32_t)(c * 48 + nbg[sl]) * 4 + ks) * 32 + lane); \
                uint2 bh = Bhi[bidx];                                             \
                uint2 bl = Blo[bidx];                                             \
                _Pragma("unroll")                                                 \
                for (int f = 0; f < 2; f++) {                                     \
                    mma16816(acc[f][sl], afh[f], bh.x, bh.y);                     \
                    mma16816(acc[f][sl], afh[f], bl.x, bl.y);                     \
                    mma16816(acc[f][sl], afl[f], bh.x, bh.y);                     \
                }                                                                 \
            }                                                                     \
        }                                                                         \
    }

__global__ void __launch_bounds__(THREADS, 1)
decoder_kernel(
    const float* __restrict__ z, const float* __restrict__ chem,
    const int*   __restrict__ edge, const int* __restrict__ mask,
    const float* __restrict__ sb2, const float* __restrict__ cb2,
    const float* __restrict__ mb2, const float* __restrict__ pw,
    float* __restrict__ out, int E)
{
    __shared__ __align__(16) char Asm[2][2][AREG];
    __shared__ float red[NWARP_N][3][TILE_E];
    __shared__ int   Ssrc[TILE_E], Sdst[TILE_E];
    __shared__ float Sbv[TILE_E];

    const int tid  = threadIdx.x;
    const int wid  = tid >> 5;
    const int lane = tid & 31;
    const int nw   = wid & 7;
    const int mw   = wid >> 3;
    const int ebase = blockIdx.x * TILE_E;

    // slot -> global nb: slot0 structural, slots1-3 chemical, slots4-5 combined
    const int nbg[NB_PER_W] = { nw, 8 + nw * 3, 9 + nw * 3, 10 + nw * 3,
                                32 + nw * 2, 33 + nw * 2 };

    if (tid < TILE_E) {
        int ge = ebase + tid;
        int s = 0, d = 0;
        float bv = 0.f;
        if (ge < E) {
            s  = edge[2 * ge + 0];
            d  = edge[2 * ge + 1];
            bv = (float)(mask[s] * mask[d]);
        }
        Ssrc[tid] = s; Sdst[tid] = d; Sbv[tid] = bv;
    }
    for (int i = tid; i < NWARP_N * 3 * TILE_E; i += THREADS)
        ((float*)red)[i] = 0.f;
    __syncthreads();

    // gather mapping: e = tid/8, q = tid%8 (8-k slice = 2 float4)
    const int ge_ = tid >> 3;
    const int q   = tid & 7;
    const int r   = ge_ & 15;
    const int fm  = ge_ >> 4;
    const uint32_t abase = (uint32_t)(fm * 4 + (q >> 1)) * ABLK
                         + (uint32_t)((r & 7) * 64 + (r >> 3) * 4 + (q & 1) * 8);
    const int srow = Ssrc[ge_];
    const int drow = Sdst[ge_];

    float4 ga[2], gb[2];
    {
        const float* sp = z + (size_t)srow * 128 + q * 8;
        const float* dp = z + (size_t)drow * 128 + q * 8;
        ga[0] = *(const float4*)(sp);     ga[1] = *(const float4*)(sp + 4);
        gb[0] = *(const float4*)(dp);     gb[1] = *(const float4*)(dp + 4);
    }

    float acc[2][NB_PER_W][4];
    #pragma unroll
    for (int a = 0; a < 2; a++)
        #pragma unroll
        for (int b = 0; b < NB_PER_W; b++)
            #pragma unroll
            for (int qq = 0; qq < 4; qq++) acc[a][b][qq] = 0.f;

    const uint2* __restrict__ Bhi = (const uint2*)g_Bp_hi;
    const uint2* __restrict__ Blo = (const uint2*)g_Bp_lo;

    #pragma unroll 1
    for (int c = 0; c < NCH; c++) {
        // ---- stage chunk c ----
        {
            char* sah = Asm[c & 1][0];
            char* sal = Asm[c & 1][1];
            #pragma unroll
            for (int i = 0; i < 2; i++) {
                float p0 = ga[i].x * gb[i].x;
                float p1 = ga[i].y * gb[i].y;
                float p2 = ga[i].z * gb[i].z;
                float p3 = ga[i].w * gb[i].w;
                __nv_bfloat16 h0 = __float2bfloat16(p0), h1 = __float2bfloat16(p1);
                __nv_bfloat16 h2 = __float2bfloat16(p2), h3 = __float2bfloat16(p3);
                float l0 = p0 - __bfloat162float(h0);
                float l1 = p1 - __bfloat162float(h1);
                float l2 = p2 - __bfloat162float(h2);
                float l3 = p3 - __bfloat162float(h3);
                uint32_t hi01 = ((uint32_t)__bfloat16_as_ushort(h0)) | ((uint32_t)__bfloat16_as_ushort(h1) << 16);
                uint32_t hi23 = ((uint32_t)__bfloat16_as_ushort(h2)) | ((uint32_t)__bfloat16_as_ushort(h3) << 16);
                uint32_t lo01 = pack_bf16x2(l0, l1);
                uint32_t lo23 = pack_bf16x2(l2, l3);
                uint32_t a0 = abase + (uint32_t)(i * 32);
                uint32_t a1 = a0 + 16;
                *(uint32_t*)(sah + a0) = hi01;
                *(uint32_t*)(sah + a1) = hi23;
                *(uint32_t*)(sal + a0) = lo01;
                *(uint32_t*)(sal + a1) = lo23;
            }
        }
        __syncthreads();

        // ---- prefetch gather for chunk c+1 ----
        if (c + 1 < NCH) {
            int cn = c + 1;
            const float* basep = (cn < 2) ? z : chem;
            int ldr = (cn < 2) ? 128 : 768;
            int kb  = (cn < 2) ? cn * 64 : (cn - 2) * 64;
            const float* sp = basep + (size_t)srow * ldr + kb + q * 8;
            const float* dp = basep + (size_t)drow * ldr + kb + q * 8;
            ga[0] = *(const float4*)(sp);     ga[1] = *(const float4*)(sp + 4);
            gb[0] = *(const float4*)(dp);     gb[1] = *(const float4*)(dp + 4);
        }

        // ---- MMA: only non-zero weight blocks ----
        {
            const char* ah = Asm[c & 1][0];
            const char* al = Asm[c & 1][1];
            if (c < 2) {
                MMA_CHUNK(3, { 0, 4, 5 })          // structural + combined cols
            } else {
                MMA_CHUNK(5, { 1, 2, 3, 4, 5 })    // chemical + combined cols
            }
        }
    }
    __syncthreads();

    // ---- epilogue ----
    {
        const int qc = (lane & 3) * 2;
        float ps[4][3];
        #pragma unroll
        for (int s = 0; s < 4; s++)
            #pragma unroll
            for (int p = 0; p < 3; p++) ps[s][p] = 0.f;

        #pragma unroll
        for (int sl = 0; sl < NB_PER_W; sl++) {
            int col0 = nbg[sl] * 8;
            int p = (sl == 0) ? 0 : (sl < 4) ? 1 : 2;
            float bb0 = g_b1[col0 + qc],     bb1 = g_b1[col0 + qc + 1];
            float ww0 = g_w2[col0 + qc],     ww1 = g_w2[col0 + qc + 1];
            #pragma unroll
            for (int f = 0; f < 2; f++) {
                const float* a = acc[f][sl];
                ps[f * 2 + 0][p] += fmaxf(a[0] + bb0, 0.f) * ww0 + fmaxf(a[1] + bb1, 0.f) * ww1;
                ps[f * 2 + 1][p] += fmaxf(a[2] + bb0, 0.f) * ww0 + fmaxf(a[3] + bb1, 0.f) * ww1;
            }
        }
        #pragma unroll
        for (int s = 0; s < 4; s++)
            #pragma unroll
            for (int p = 0; p < 3; p++) {
                float v = ps[s][p];
                v += __shfl_xor_sync(0xffffffffu, v, 1);
                v += __shfl_xor_sync(0xffffffffu, v, 2);
                ps[s][p] = v;
            }
        if ((lane & 3) == 0) {
            #pragma unroll
            for (int f = 0; f < 2; f++)
                #pragma unroll
                for (int rr = 0; rr < 2; rr++) {
                    int el = (mw * 2 + f) * 16 + (lane >> 2) + rr * 8;
                    #pragma unroll
                    for (int p = 0; p < 3; p++)
                        red[nw][p][el] += ps[f * 2 + rr][p];
                }
        }
    }
    __syncthreads();

    if (tid < TILE_E && ebase + tid < E) {
        float s0 = 0.f, s1 = 0.f, s2 = 0.f;
        #pragma unroll
        for (int w = 0; w < NWARP_N; w++) {
            s0 += red[w][0][tid];
            s1 += red[w][1][tid];
            s2 += red[w][2][tid];
        }
        float p0 = pw[0], p1 = pw[1], p2 = pw[2];
        float mx = fmaxf(p0, fmaxf(p1, p2));
        float e0 = expf(p0 - mx), e1 = expf(p1 - mx), e2 = expf(p2 - mx);
        float inv = 1.f / (e0 + e1 + e2);
        float ss = s0 + sb2[0];
        float sc = s1 + cb2[0];
        float sm = s2 + mb2[0];
        float comb = (e0 * ss + e1 * sc + e2 * sm) * inv;
        out[ebase + tid] = (Sbv[tid] > 0.5f) ? comb : ss;
    }
}

extern "C" void kernel_launch(void* const* d_in, const int* in_sizes, int n_in,
                              void* d_out, int out_size)
{
    const float* z    = (const float*)d_in[0];
    const float* chem = (const float*)d_in[1];
    const int*   edge = (const int*)d_in[2];
    const int*   mask = (const int*)d_in[3];
    const float* sw1  = (const float*)d_in[4];
    const float* sb1  = (const float*)d_in[5];
    const float* sw2  = (const float*)d_in[6];
    const float* sb2  = (const float*)d_in[7];
    const float* cw1  = (const float*)d_in[8];
    const float* cb1  = (const float*)d_in[9];
    const float* cw2  = (const float*)d_in[10];
    const float* cb2  = (const float*)d_in[11];
    const float* mw1  = (const float*)d_in[12];
    const float* mb1  = (const float*)d_in[13];
    const float* mw2  = (const float*)d_in[14];
    const float* mb2  = (const float*)d_in[15];
    const float* pw   = (const float*)d_in[16];
    float*       out  = (float*)d_out;

    const int E = in_sizes[2] / 2;

    {
        int total = KTOT * HTOT + HTOT;
        pack_kernel<<<(total + 255) / 256, 256>>>(sw1, sb1, sw2,
                                                  cw1, cb1, cw2,
                                                  mw1, mb1, mw2);
    }

    const int nblocks = (E + TILE_E - 1) / TILE_E;
    decoder_kernel<<<nblocks, THREADS>>>(
        z, chem, edge, mask, sb2, cb2, mb2, pw, out, E);
}

// round 11
// speedup vs baseline: 1.4984x; 1.0107x over previous
#include <cuda_runtime.h>
#include <cuda_bf16.h>
#include <cstdint>

#define THREADS 512
#define TILE_E  64              // M per CTA
#define KTOT    896
#define HTOT    384
#define NCH     14              // 896/64
#define NWARP_N 8
#define NB_PER_W 6              // 1 structural + 3 chemical + 2 combined

// ---------- packed weights (built per launch) ----------
// Chunk-contiguous active-block layout, hi/lo interleaved per 16B:
//   chunk base: c<2 ? c*49152 : 98304 + (c-2)*81920
//   within chunk: ((abi*4 + ks)*32 + lane)*16  + [hi: 2*(reg*2+pair)]  [lo: 8 + ...]
// z-chunk active blocks: structural nb 0..7 (abi=nb), combined nb 32..47 (abi=8+nb-32)  -> 24 blocks, 49152 B
// chem-chunk active:     chemical  nb 8..31 (abi=nb-8), combined (abi=24+nb-32)         -> 40 blocks, 81920 B
#define BPK_TOTAL (2 * 49152 + 12 * 81920)
__device__ __align__(16) unsigned char g_Bpk[BPK_TOTAL];
__device__ float g_b1[HTOT];
__device__ float g_w2[HTOT];

__global__ void pack_kernel(
    const float* __restrict__ sw1, const float* __restrict__ sb1, const float* __restrict__ sw2,
    const float* __restrict__ cw1, const float* __restrict__ cb1, const float* __restrict__ cw2,
    const float* __restrict__ mw1, const float* __restrict__ mb1, const float* __restrict__ mw2)
{
    int idx = blockIdx.x * blockDim.x + threadIdx.x;
    if (idx < KTOT * HTOT) {
        int k = idx / HTOT;
        int j = idx - k * HTOT;
        float v = 0.f;
        if (j < 64) {
            if (k < 128) v = sw1[k * 64 + j];
        } else if (j < 256) {
            if (k >= 128) v = cw1[(k - 128) * 192 + (j - 64)];
        } else {
            v = mw1[k * 128 + (j - 256)];
        }
        int c  = k >> 6;
        int nb = j >> 3;
        int abi = -1;
        if (c < 2) {
            if (nb < 8)        abi = nb;
            else if (nb >= 32) abi = 8 + (nb - 32);
        } else {
            if (nb >= 32)      abi = 24 + (nb - 32);
            else if (nb >= 8)  abi = nb - 8;
        }
        if (abi >= 0) {
            __nv_bfloat16 vh = __float2bfloat16(v);
            __nv_bfloat16 vl = __float2bfloat16(v - __bfloat162float(vh));
            int kk = k & 63;
            int ks = kk >> 4;
            int kr = kk & 15;
            int nr = j & 7;
            int lane = nr * 4 + ((kr & 7) >> 1);
            int reg  = kr >> 3;
            int pair = kr & 1;
            uint32_t cbase = (c < 2) ? (uint32_t)c * 49152u
                                     : 98304u + (uint32_t)(c - 2) * 81920u;
            uint32_t slot16 = cbase + (((uint32_t)abi * 4 + ks) * 32 + lane) * 16;
            uint32_t sub = 2 * (reg * 2 + pair);
            *(__nv_bfloat16*)(g_Bpk + slot16 + sub)     = vh;
            *(__nv_bfloat16*)(g_Bpk + slot16 + 8 + sub) = vl;
        }
    } else if (idx < KTOT * HTOT + HTOT) {
        int j = idx - KTOT * HTOT;
        float b, w;
        if (j < 64)       { b = sb1[j];       w = sw2[j]; }
        else if (j < 256) { b = cb1[j - 64];  w = cw2[j - 64]; }
        else              { b = mb1[j - 256]; w = mw2[j - 256]; }
        g_b1[j] = b;
        g_w2[j] = w;
    }
}

__device__ __forceinline__ void mma16816(float* d, const uint32_t* a, const uint32_t b0, const uint32_t b1) {
    asm volatile(
        "mma.sync.aligned.m16n8k16.row.col.f32.bf16.bf16.f32 "
        "{%0,%1,%2,%3}, {%4,%5,%6,%7}, {%8,%9}, {%0,%1,%2,%3};"
        : "+f"(d[0]), "+f"(d[1]), "+f"(d[2]), "+f"(d[3])
        : "r"(a[0]), "r"(a[1]), "r"(a[2]), "r"(a[3]), "r"(b0), "r"(b1));
}

__device__ __forceinline__ uint32_t pack_bf16x2(float x, float y) {
    __nv_bfloat162 h = __floats2bfloat162_rn(x, y);
    return *reinterpret_cast<uint32_t*>(&h);
}

__device__ __forceinline__ void cp_async16(uint32_t saddr, const void* gptr) {
    asm volatile("cp.async.cg.shared.global [%0], [%1], 16;" :: "r"(saddr), "l"(gptr));
}
#define CP_COMMIT() asm volatile("cp.async.commit_group;" ::: "memory")
#define CP_WAIT0()  asm volatile("cp.async.wait_group 0;" ::: "memory")

#define ABLK 528
#define AREG (16 * ABLK)              // 8448 per split
#define BBUF 81920                    // max chunk B bytes (chem)

// dynamic smem layout
#define A_OFF    0                    // [2 dbuf][2 split][AREG]  = 33792
#define B_OFF    (4 * AREG)           // [2 dbuf][BBUF]           = 163840
#define RED_OFF  (B_OFF + 2 * BBUF)   // [8][3][64] f32           = 6144
#define SRC_OFF  (RED_OFF + 6144)
#define DST_OFF  (SRC_OFF + 256)
#define BV_OFF   (DST_OFF + 256)
#define SM_TOTAL (BV_OFF + 256)

// MMA block: A frags from smem, B frag = single LDS.128 (hi pair + lo pair).
// slist/alist are constexpr-foldable after inlining (call sites pass local
// const arrays with literal-from-nw contents).
template <int NACT>
__device__ __forceinline__ void mma_chunk(
    float acc[2][NB_PER_W][4],
    const char* ah, const char* al, const char* bB,
    int mw, int lane, const int* slist, const int* alist)
{
    #pragma unroll
    for (int ks = 0; ks < 4; ks++) {
        uint32_t afh[2][4], afl[2][4];
        #pragma unroll
        for (int f = 0; f < 2; f++) {
            uint32_t boff = (uint32_t)((mw * 2 + f) * 4 + ks) * ABLK + lane * 16;
            uint4 vh = *(const uint4*)(ah + boff);
            uint4 vl = *(const uint4*)(al + boff);
            afh[f][0] = vh.x; afh[f][1] = vh.y; afh[f][2] = vh.z; afh[f][3] = vh.w;
            afl[f][0] = vl.x; afl[f][1] = vl.y; afl[f][2] = vl.z; afl[f][3] = vl.w;
        }
        #pragma unroll
        for (int i = 0; i < NACT; i++) {
            const int sl = slist[i];
            uint4 v = *(const uint4*)(bB + (((uint32_t)alist[i] * 4 + ks) * 32 + lane) * 16);
            #pragma unroll
            for (int f = 0; f < 2; f++) {
                mma16816(acc[f][sl], afh[f], v.x, v.y);   // hi*hi
                mma16816(acc[f][sl], afh[f], v.z, v.w);   // hi*lo
                mma16816(acc[f][sl], afl[f], v.x, v.y);   // lo*hi
            }
        }
    }
}

__global__ void __launch_bounds__(THREADS, 1)
decoder_kernel(
    const float* __restrict__ z, const float* __restrict__ chem,
    const int*   __restrict__ edge, const int* __restrict__ mask,
    const float* __restrict__ sb2, const float* __restrict__ cb2,
    const float* __restrict__ mb2, const float* __restrict__ pw,
    float* __restrict__ out, int E)
{
    extern __shared__ __align__(16) char smem[];
    uint32_t smem_u32;
    asm("{ .reg .u64 t; cvta.to.shared.u64 t, %1; cvt.u32.u64 %0, t; }"
        : "=r"(smem_u32) : "l"(smem));

    const int tid  = threadIdx.x;
    const int wid  = tid >> 5;
    const int lane = tid & 31;
    const int nw   = wid & 7;
    const int mw   = wid >> 3;
    const int ebase = blockIdx.x * TILE_E;

    int*   Ssrc = (int*)(smem + SRC_OFF);
    int*   Sdst = (int*)(smem + DST_OFF);
    float* Sbv  = (float*)(smem + BV_OFF);
    float* red  = (float*)(smem + RED_OFF);

    if (tid < TILE_E) {
        int ge = ebase + tid;
        int s = 0, d = 0;
        float bv = 0.f;
        if (ge < E) {
            s  = edge[2 * ge + 0];
            d  = edge[2 * ge + 1];
            bv = (float)(mask[s] * mask[d]);
        }
        Ssrc[tid] = s; Sdst[tid] = d; Sbv[tid] = bv;
    }
    for (int i = tid; i < NWARP_N * 3 * TILE_E; i += THREADS)
        red[i] = 0.f;
    __syncthreads();

    // gather mapping: e = tid/8, q = tid%8 (8-k slice = 2 float4)
    const int ge_ = tid >> 3;
    const int q   = tid & 7;
    const int r   = ge_ & 15;
    const int fm  = ge_ >> 4;
    const uint32_t abase = (uint32_t)(fm * 4 + (q >> 1)) * ABLK
                         + (uint32_t)((r & 7) * 64 + (r >> 3) * 4 + (q & 1) * 8);
    const int srow = Ssrc[ge_];
    const int drow = Sdst[ge_];

    // active slot/block lists (contents fold to literals after inlining)
    const int sl_z[3] = { 0, 4, 5 };
    const int ab_z[3] = { nw, 8 + 2 * nw, 9 + 2 * nw };
    const int sl_c[5] = { 1, 2, 3, 4, 5 };
    const int ab_c[5] = { 3 * nw, 3 * nw + 1, 3 * nw + 2, 24 + 2 * nw, 25 + 2 * nw };

    float4 ga[2], gb[2];
    {
        const float* sp = z + (size_t)srow * 128 + q * 8;
        const float* dp = z + (size_t)drow * 128 + q * 8;
        ga[0] = *(const float4*)(sp);     ga[1] = *(const float4*)(sp + 4);
        gb[0] = *(const float4*)(dp);     gb[1] = *(const float4*)(dp + 4);
    }
    // prologue: B(0) cp.async (z-chunk: 49152 B)
    {
        for (int i = tid; i < 49152 / 16; i += THREADS)
            cp_async16(smem_u32 + B_OFF + i * 16, g_Bpk + i * 16);
        CP_COMMIT();
    }

    float acc[2][NB_PER_W][4];
    #pragma unroll
    for (int a = 0; a < 2; a++)
        #pragma unroll
        for (int b = 0; b < NB_PER_W; b++)
            #pragma unroll
            for (int qq = 0; qq < 4; qq++) acc[a][b][qq] = 0.f;

    #pragma unroll 1
    for (int c = 0; c < NCH; c++) {
        // ---- stage A(c): split bf16 hi/lo, fragment order ----
        {
            char* sah = smem + A_OFF + ((c & 1) * 2 + 0) * AREG;
            char* sal = smem + A_OFF + ((c & 1) * 2 + 1) * AREG;
            #pragma unroll
            for (int i = 0; i < 2; i++) {
                float p0 = ga[i].x * gb[i].x;
                float p1 = ga[i].y * gb[i].y;
                float p2 = ga[i].z * gb[i].z;
                float p3 = ga[i].w * gb[i].w;
                __nv_bfloat16 h0 = __float2bfloat16(p0), h1 = __float2bfloat16(p1);
                __nv_bfloat16 h2 = __float2bfloat16(p2), h3 = __float2bfloat16(p3);
                float l0 = p0 - __bfloat162float(h0);
                float l1 = p1 - __bfloat162float(h1);
                float l2 = p2 - __bfloat162float(h2);
                float l3 = p3 - __bfloat162float(h3);
                uint32_t hi01 = ((uint32_t)__bfloat16_as_ushort(h0)) | ((uint32_t)__bfloat16_as_ushort(h1) << 16);
                uint32_t hi23 = ((uint32_t)__bfloat16_as_ushort(h2)) | ((uint32_t)__bfloat16_as_ushort(h3) << 16);
                uint32_t lo01 = pack_bf16x2(l0, l1);
                uint32_t lo23 = pack_bf16x2(l2, l3);
                uint32_t a0 = abase + (uint32_t)(i * 32);
                uint32_t a1 = a0 + 16;
                *(uint32_t*)(sah + a0) = hi01;
                *(uint32_t*)(sah + a1) = hi23;
                *(uint32_t*)(sal + a0) = lo01;
                *(uint32_t*)(sal + a1) = lo23;
            }
        }
        CP_WAIT0();          // B(c) resident for this thread; barrier covers the rest
        __syncthreads();

        // ---- issue cp.async for B(c+1) into the other buffer ----
        if (c + 1 < NCH) {
            int cn = c + 1;
            uint32_t nb16  = ((cn < 2) ? 49152u : 81920u) >> 4;
            uint32_t cbase = (cn < 2) ? (uint32_t)cn * 49152u
                                      : 98304u + (uint32_t)(cn - 2) * 81920u;
            uint32_t bdst = smem_u32 + B_OFF + (uint32_t)(cn & 1) * BBUF;
            const unsigned char* gsrc = g_Bpk + cbase;
            for (uint32_t i = tid; i < nb16; i += THREADS)
                cp_async16(bdst + i * 16, gsrc + i * 16);
            CP_COMMIT();
        }

        // ---- prefetch gather for A(c+1) ----
        if (c + 1 < NCH) {
            int cn = c + 1;
            const float* basep = (cn < 2) ? z : chem;
            int ldr = (cn < 2) ? 128 : 768;
            int kb  = (cn < 2) ? cn * 64 : (cn - 2) * 64;
            const float* sp = basep + (size_t)srow * ldr + kb + q * 8;
            const float* dp = basep + (size_t)drow * ldr + kb + q * 8;
            ga[0] = *(const float4*)(sp);     ga[1] = *(const float4*)(sp + 4);
            gb[0] = *(const float4*)(dp);     gb[1] = *(const float4*)(dp + 4);
        }

        // ---- MMA over active blocks; B from smem (1 LDS.128 per slot) ----
        {
            const char* ah = smem + A_OFF + ((c & 1) * 2 + 0) * AREG;
            const char* al = smem + A_OFF + ((c & 1) * 2 + 1) * AREG;
            const char* bB = smem + B_OFF + (c & 1) * BBUF;
            if (c < 2) mma_chunk<3>(acc, ah, al, bB, mw, lane, sl_z, ab_z);
            else       mma_chunk<5>(acc, ah, al, bB, mw, lane, sl_c, ab_c);
        }
    }
    __syncthreads();

    // ---- epilogue ----
    {
        const int nbg[NB_PER_W] = { nw, 8 + nw * 3, 9 + nw * 3, 10 + nw * 3,
                                    32 + nw * 2, 33 + nw * 2 };
        const int qc = (lane & 3) * 2;
        float ps[4][3];
        #pragma unroll
        for (int s = 0; s < 4; s++)
            #pragma unroll
            for (int p = 0; p < 3; p++) ps[s][p] = 0.f;

        #pragma unroll
        for (int sl = 0; sl < NB_PER_W; sl++) {
            int col0 = nbg[sl] * 8;
            int p = (sl == 0) ? 0 : (sl < 4) ? 1 : 2;
            float bb0 = g_b1[col0 + qc],     bb1 = g_b1[col0 + qc + 1];
            float ww0 = g_w2[col0 + qc],     ww1 = g_w2[col0 + qc + 1];
            #pragma unroll
            for (int f = 0; f < 2; f++) {
                const float* a = acc[f][sl];
                ps[f * 2 + 0][p] += fmaxf(a[0] + bb0, 0.f) * ww0 + fmaxf(a[1] + bb1, 0.f) * ww1;
                ps[f * 2 + 1][p] += fmaxf(a[2] + bb0, 0.f) * ww0 + fmaxf(a[3] + bb1, 0.f) * ww1;
            }
        }
        #pragma unroll
        for (int s = 0; s < 4; s++)
            #pragma unroll
            for (int p = 0; p < 3; p++) {
                float v = ps[s][p];
                v += __shfl_xor_sync(0xffffffffu, v, 1);
                v += __shfl_xor_sync(0xffffffffu, v, 2);
                ps[s][p] = v;
            }
        if ((lane & 3) == 0) {
            #pragma unroll
            for (int f = 0; f < 2; f++)
                #pragma unroll
                for (int rr = 0; rr < 2; rr++) {
                    int el = (mw * 2 + f) * 16 + (lane >> 2) + rr * 8;
                    #pragma unroll
                    for (int p = 0; p < 3; p++)
                        red[(nw * 3 + p) * TILE_E + el] += ps[f * 2 + rr][p];
                }
        }
    }
    __syncthreads();

    if (tid < TILE_E && ebase + tid < E) {
        float s0 = 0.f, s1 = 0.f, s2 = 0.f;
        #pragma unroll
        for (int w = 0; w < NWARP_N; w++) {
            s0 += red[(w * 3 + 0) * TILE_E + tid];
            s1 += red[(w * 3 + 1) * TILE_E + tid];
            s2 += red[(w * 3 + 2) * TILE_E + tid];
        }
        float p0 = pw[0], p1 = pw[1], p2 = pw[2];
        float mx = fmaxf(p0, fmaxf(p1, p2));
        float e0 = expf(p0 - mx), e1 = expf(p1 - mx), e2 = expf(p2 - mx);
        float inv = 1.f / (e0 + e1 + e2);
        float ss = s0 + sb2[0];
        float sc = s1 + cb2[0];
        float sm = s2 + mb2[0];
        float comb = (e0 * ss + e1 * sc + e2 * sm) * inv;
        out[ebase + tid] = (Sbv[tid] > 0.5f) ? comb : ss;
    }
}

extern "C" void kernel_launch(void* const* d_in, const int* in_sizes, int n_in,
                              void* d_out, int out_size)
{
    const float* z    = (const float*)d_in[0];
    const float* chem = (const float*)d_in[1];
    const int*   edge = (const int*)d_in[2];
    const int*   mask = (const int*)d_in[3];
    const float* sw1  = (const float*)d_in[4];
    const float* sb1  = (const float*)d_in[5];
    const float* sw2  = (const float*)d_in[6];
    const float* sb2  = (const float*)d_in[7];
    const float* cw1  = (const float*)d_in[8];
    const float* cb1  = (const float*)d_in[9];
    const float* cw2  = (const float*)d_in[10];
    const float* cb2  = (const float*)d_in[11];
    const float* mw1  = (const float*)d_in[12];
    const float* mb1  = (const float*)d_in[13];
    const float* mw2  = (const float*)d_in[14];
    const float* mb2  = (const float*)d_in[15];
    const float* pw   = (const float*)d_in[16];
    float*       out  = (float*)d_out;

    const int E = in_sizes[2] / 2;

    {
        int total = KTOT * HTOT + HTOT;
        pack_kernel<<<(total + 255) / 256, 256>>>(sw1, sb1, sw2,
                                                  cw1, cb1, cw2,
                                                  mw1, mb1, mw2);
    }

    cudaFuncSetAttribute(decoder_kernel,
                         cudaFuncAttributeMaxDynamicSharedMemorySize, SM_TOTAL);
    const int nblocks = (E + TILE_E - 1) / TILE_E;
    decoder_kernel<<<nblocks, THREADS, SM_TOTAL>>>(
        z, chem, edge, mask, sb2, cb2, mb2, pw, out, E);
}

// round 12
// speedup vs baseline: 3.7483x; 2.5015x over previous
#include <cuda_runtime.h>
#include <cuda_bf16.h>
#include <cstdint>

#define THREADS 512
#define TILE_E  64
#define KTOT    896
#define HTOT    384
#define NCH     14
#define NWARP_N 8
#define NB_PER_W 6
#define E_MAX   200704

// ---------- packed weights ----------
#define BPK_TOTAL (2 * 49152 + 12 * 81920)
__device__ __align__(16) unsigned char g_Bpk[BPK_TOTAL];
__device__ float g_b1[HTOT];
__device__ float g_w2[HTOT];

// ---------- edge compaction ----------
__device__ int g_valid[E_MAX];
__device__ int g_invalid[E_MAX];
__device__ int g_cnt[2];

__global__ void zero_kernel() { g_cnt[0] = 0; g_cnt[1] = 0; }

__global__ void compact_kernel(const int* __restrict__ edge,
                               const int* __restrict__ mask, int E)
{
    int e = blockIdx.x * blockDim.x + threadIdx.x;
    if (e < E) {
        int s = edge[2 * e], d = edge[2 * e + 1];
        if (mask[s] && mask[d]) { int p = atomicAdd(&g_cnt[0], 1); g_valid[p] = e; }
        else                    { int p = atomicAdd(&g_cnt[1], 1); g_invalid[p] = e; }
    }
}

__global__ void pack_kernel(
    const float* __restrict__ sw1, const float* __restrict__ sb1, const float* __restrict__ sw2,
    const float* __restrict__ cw1, const float* __restrict__ cb1, const float* __restrict__ cw2,
    const float* __restrict__ mw1, const float* __restrict__ mb1, const float* __restrict__ mw2)
{
    int idx = blockIdx.x * blockDim.x + threadIdx.x;
    if (idx < KTOT * HTOT) {
        int k = idx / HTOT;
        int j = idx - k * HTOT;
        float v = 0.f;
        if (j < 64) {
            if (k < 128) v = sw1[k * 64 + j];
        } else if (j < 256) {
            if (k >= 128) v = cw1[(k - 128) * 192 + (j - 64)];
        } else {
            v = mw1[k * 128 + (j - 256)];
        }
        int c  = k >> 6;
        int nb = j >> 3;
        int abi = -1;
        if (c < 2) {
            if (nb < 8)        abi = nb;
            else if (nb >= 32) abi = 8 + (nb - 32);
        } else {
            if (nb >= 32)      abi = 24 + (nb - 32);
            else if (nb >= 8)  abi = nb - 8;
        }
        if (abi >= 0) {
            __nv_bfloat16 vh = __float2bfloat16(v);
            __nv_bfloat16 vl = __float2bfloat16(v - __bfloat162float(vh));
            int kk = k & 63;
            int ks = kk >> 4;
            int kr = kk & 15;
            int nr = j & 7;
            int lane = nr * 4 + ((kr & 7) >> 1);
            int reg  = kr >> 3;
            int pair = kr & 1;
            uint32_t cbase = (c < 2) ? (uint32_t)c * 49152u
                                     : 98304u + (uint32_t)(c - 2) * 81920u;
            uint32_t slot16 = cbase + (((uint32_t)abi * 4 + ks) * 32 + lane) * 16;
            uint32_t sub = 2 * (reg * 2 + pair);
            *(__nv_bfloat16*)(g_Bpk + slot16 + sub)     = vh;
            *(__nv_bfloat16*)(g_Bpk + slot16 + 8 + sub) = vl;
        }
    } else if (idx < KTOT * HTOT + HTOT) {
        int j = idx - KTOT * HTOT;
        float b, w;
        if (j < 64)       { b = sb1[j];       w = sw2[j]; }
        else if (j < 256) { b = cb1[j - 64];  w = cw2[j - 64]; }
        else              { b = mb1[j - 256]; w = mw2[j - 256]; }
        g_b1[j] = b;
        g_w2[j] = w;
    }
}

__device__ __forceinline__ void mma16816(float* d, const uint32_t* a, const uint32_t b0, const uint32_t b1) {
    asm volatile(
        "mma.sync.aligned.m16n8k16.row.col.f32.bf16.bf16.f32 "
        "{%0,%1,%2,%3}, {%4,%5,%6,%7}, {%8,%9}, {%0,%1,%2,%3};"
        : "+f"(d[0]), "+f"(d[1]), "+f"(d[2]), "+f"(d[3])
        : "r"(a[0]), "r"(a[1]), "r"(a[2]), "r"(a[3]), "r"(b0), "r"(b1));
}

__device__ __forceinline__ uint32_t pack_bf16x2(float x, float y) {
    __nv_bfloat162 h = __floats2bfloat162_rn(x, y);
    return *reinterpret_cast<uint32_t*>(&h);
}

__device__ __forceinline__ void cp_async16(uint32_t saddr, const void* gptr) {
    asm volatile("cp.async.cg.shared.global [%0], [%1], 16;" :: "r"(saddr), "l"(gptr));
}
#define CP_COMMIT() asm volatile("cp.async.commit_group;" ::: "memory")
#define CP_WAIT0()  asm volatile("cp.async.wait_group 0;" ::: "memory")

#define ABLK 528
#define AREG (16 * ABLK)
#define BBUF 81920

#define A_OFF    0
#define B_OFF    (4 * AREG)
#define RED_OFF  (B_OFF + 2 * BBUF)
#define SRC_OFF  (RED_OFF + 6144)
#define DST_OFF  (SRC_OFF + 256)
#define GE_OFF   (DST_OFF + 256)
#define SM_TOTAL (GE_OFF + 256)

template <int NACT>
__device__ __forceinline__ void mma_chunk(
    float acc[2][NB_PER_W][4],
    const char* ah, const char* al, const char* bB,
    int mw, int lane, const int* slist, const int* alist)
{
    #pragma unroll
    for (int ks = 0; ks < 4; ks++) {
        uint32_t afh[2][4], afl[2][4];
        #pragma unroll
        for (int f = 0; f < 2; f++) {
            uint32_t boff = (uint32_t)((mw * 2 + f) * 4 + ks) * ABLK + lane * 16;
            uint4 vh = *(const uint4*)(ah + boff);
            uint4 vl = *(const uint4*)(al + boff);
            afh[f][0] = vh.x; afh[f][1] = vh.y; afh[f][2] = vh.z; afh[f][3] = vh.w;
            afl[f][0] = vl.x; afl[f][1] = vl.y; afl[f][2] = vl.z; afl[f][3] = vl.w;
        }
        #pragma unroll
        for (int i = 0; i < NACT; i++) {
            const int sl = slist[i];
            uint4 v = *(const uint4*)(bB + (((uint32_t)alist[i] * 4 + ks) * 32 + lane) * 16);
            #pragma unroll
            for (int f = 0; f < 2; f++) {
                mma16816(acc[f][sl], afh[f], v.x, v.y);
                mma16816(acc[f][sl], afh[f], v.z, v.w);
                mma16816(acc[f][sl], afl[f], v.x, v.y);
            }
        }
    }
}

// FULL: all 3 paths on valid edges (out = softmax combine).
// STRUCT: structural path only on invalid edges (out = structural score).
template <bool FULL>
__global__ void __launch_bounds__(THREADS, 1)
decoder_kernel(
    const float* __restrict__ z, const float* __restrict__ chem,
    const int*   __restrict__ edge,
    const float* __restrict__ sb2, const float* __restrict__ cb2,
    const float* __restrict__ mb2, const float* __restrict__ pw,
    float* __restrict__ out)
{
    const int nv = g_cnt[FULL ? 0 : 1];
    const int ebase = blockIdx.x * TILE_E;
    if (ebase >= nv) return;

    extern __shared__ __align__(16) char smem[];
    uint32_t smem_u32;
    asm("{ .reg .u64 t; cvta.to.shared.u64 t, %1; cvt.u32.u64 %0, t; }"
        : "=r"(smem_u32) : "l"(smem));

    const int tid  = threadIdx.x;
    const int wid  = tid >> 5;
    const int lane = tid & 31;
    const int nw   = wid & 7;
    const int mw   = wid >> 3;

    const int* elist = FULL ? g_valid : g_invalid;
    const int  NCHE  = FULL ? NCH : 2;
    const uint32_t B0SZ = FULL ? 49152u : 16384u;   // structural blocks = first 16KB of z-chunk

    int*   Ssrc = (int*)(smem + SRC_OFF);
    int*   Sdst = (int*)(smem + DST_OFF);
    int*   Sge  = (int*)(smem + GE_OFF);
    float* red  = (float*)(smem + RED_OFF);

    if (tid < TILE_E) {
        int li = ebase + tid;
        int ge = elist[(li < nv) ? li : (nv - 1)];
        Sge[tid] = (li < nv) ? ge : -1;
        Ssrc[tid] = edge[2 * ge + 0];
        Sdst[tid] = edge[2 * ge + 1];
    }
    for (int i = tid; i < NWARP_N * 3 * TILE_E; i += THREADS)
        red[i] = 0.f;
    __syncthreads();

    const int ge_ = tid >> 3;
    const int q   = tid & 7;
    const int r   = ge_ & 15;
    const int fm  = ge_ >> 4;
    const uint32_t abase = (uint32_t)(fm * 4 + (q >> 1)) * ABLK
                         + (uint32_t)((r & 7) * 64 + (r >> 3) * 4 + (q & 1) * 8);
    const int srow = Ssrc[ge_];
    const int drow = Sdst[ge_];

    const int sl_z[3] = { 0, 4, 5 };
    const int ab_z[3] = { nw, 8 + 2 * nw, 9 + 2 * nw };
    const int sl_c[5] = { 1, 2, 3, 4, 5 };
    const int ab_c[5] = { 3 * nw, 3 * nw + 1, 3 * nw + 2, 24 + 2 * nw, 25 + 2 * nw };
    const int sl_s[1] = { 0 };
    const int ab_s[1] = { nw };

    float4 ga[2], gb[2];
    {
        const float* sp = z + (size_t)srow * 128 + q * 8;
        const float* dp = z + (size_t)drow * 128 + q * 8;
        ga[0] = *(const float4*)(sp);     ga[1] = *(const float4*)(sp + 4);
        gb[0] = *(const float4*)(dp);     gb[1] = *(const float4*)(dp + 4);
    }
    {
        for (uint32_t i = tid; i < B0SZ / 16; i += THREADS)
            cp_async16(smem_u32 + B_OFF + i * 16, g_Bpk + i * 16);
        CP_COMMIT();
    }

    float acc[2][NB_PER_W][4];
    #pragma unroll
    for (int a = 0; a < 2; a++)
        #pragma unroll
        for (int b = 0; b < NB_PER_W; b++)
            #pragma unroll
            for (int qq = 0; qq < 4; qq++) acc[a][b][qq] = 0.f;

    #pragma unroll 1
    for (int c = 0; c < NCHE; c++) {
        // ---- stage A(c) ----
        {
            char* sah = smem + A_OFF + ((c & 1) * 2 + 0) * AREG;
            char* sal = smem + A_OFF + ((c & 1) * 2 + 1) * AREG;
            #pragma unroll
            for (int i = 0; i < 2; i++) {
                float p0 = ga[i].x * gb[i].x;
                float p1 = ga[i].y * gb[i].y;
                float p2 = ga[i].z * gb[i].z;
                float p3 = ga[i].w * gb[i].w;
                __nv_bfloat16 h0 = __float2bfloat16(p0), h1 = __float2bfloat16(p1);
                __nv_bfloat16 h2 = __float2bfloat16(p2), h3 = __float2bfloat16(p3);
                float l0 = p0 - __bfloat162float(h0);
                float l1 = p1 - __bfloat162float(h1);
                float l2 = p2 - __bfloat162float(h2);
                float l3 = p3 - __bfloat162float(h3);
                uint32_t hi01 = ((uint32_t)__bfloat16_as_ushort(h0)) | ((uint32_t)__bfloat16_as_ushort(h1) << 16);
                uint32_t hi23 = ((uint32_t)__bfloat16_as_ushort(h2)) | ((uint32_t)__bfloat16_as_ushort(h3) << 16);
                uint32_t lo01 = pack_bf16x2(l0, l1);
                uint32_t lo23 = pack_bf16x2(l2, l3);
                uint32_t a0 = abase + (uint32_t)(i * 32);
                uint32_t a1 = a0 + 16;
                *(uint32_t*)(sah + a0) = hi01;
                *(uint32_t*)(sah + a1) = hi23;
                *(uint32_t*)(sal + a0) = lo01;
                *(uint32_t*)(sal + a1) = lo23;
            }
        }
        CP_WAIT0();
        __syncthreads();

        // ---- cp.async B(c+1) ----
        if (c + 1 < NCHE) {
            int cn = c + 1;
            uint32_t nb16, cbase;
            if (FULL) {
                nb16  = ((cn < 2) ? 49152u : 81920u) >> 4;
                cbase = (cn < 2) ? (uint32_t)cn * 49152u
                                 : 98304u + (uint32_t)(cn - 2) * 81920u;
            } else {
                nb16  = 16384u >> 4;
                cbase = (uint32_t)cn * 49152u;
            }
            uint32_t bdst = smem_u32 + B_OFF + (uint32_t)(cn & 1) * BBUF;
            const unsigned char* gsrc = g_Bpk + cbase;
            for (uint32_t i = tid; i < nb16; i += THREADS)
                cp_async16(bdst + i * 16, gsrc + i * 16);
            CP_COMMIT();
        }

        // ---- prefetch gather A(c+1) ----
        if (c + 1 < NCHE) {
            int cn = c + 1;
            const float* basep = (cn < 2) ? z : chem;
            int ldr = (cn < 2) ? 128 : 768;
            int kb  = (cn < 2) ? cn * 64 : (cn - 2) * 64;
            const float* sp = basep + (size_t)srow * ldr + kb + q * 8;
            const float* dp = basep + (size_t)drow * ldr + kb + q * 8;
            ga[0] = *(const float4*)(sp);     ga[1] = *(const float4*)(sp + 4);
            gb[0] = *(const float4*)(dp);     gb[1] = *(const float4*)(dp + 4);
        }

        // ---- MMA ----
        {
            const char* ah = smem + A_OFF + ((c & 1) * 2 + 0) * AREG;
            const char* al = smem + A_OFF + ((c & 1) * 2 + 1) * AREG;
            const char* bB = smem + B_OFF + (c & 1) * BBUF;
            if (FULL) {
                if (c < 2) mma_chunk<3>(acc, ah, al, bB, mw, lane, sl_z, ab_z);
                else       mma_chunk<5>(acc, ah, al, bB, mw, lane, sl_c, ab_c);
            } else {
                mma_chunk<1>(acc, ah, al, bB, mw, lane, sl_s, ab_s);
            }
        }
    }
    __syncthreads();

    // ---- epilogue ----
    {
        const int nbg[NB_PER_W] = { nw, 8 + nw * 3, 9 + nw * 3, 10 + nw * 3,
                                    32 + nw * 2, 33 + nw * 2 };
        const int qc = (lane & 3) * 2;
        float ps[4][3];
        #pragma unroll
        for (int s = 0; s < 4; s++)
            #pragma unroll
            for (int p = 0; p < 3; p++) ps[s][p] = 0.f;

        const int NSL = FULL ? NB_PER_W : 1;
        #pragma unroll
        for (int sl = 0; sl < NSL; sl++) {
            int col0 = nbg[sl] * 8;
            int p = (sl == 0) ? 0 : (sl < 4) ? 1 : 2;
            float bb0 = g_b1[col0 + qc],     bb1 = g_b1[col0 + qc + 1];
            float ww0 = g_w2[col0 + qc],     ww1 = g_w2[col0 + qc + 1];
            #pragma unroll
            for (int f = 0; f < 2; f++) {
                const float* a = acc[f][sl];
                ps[f * 2 + 0][p] += fmaxf(a[0] + bb0, 0.f) * ww0 + fmaxf(a[1] + bb1, 0.f) * ww1;
                ps[f * 2 + 1][p] += fmaxf(a[2] + bb0, 0.f) * ww0 + fmaxf(a[3] + bb1, 0.f) * ww1;
            }
        }
        #pragma unroll
        for (int s = 0; s < 4; s++)
            #pragma unroll
            for (int p = 0; p < 3; p++) {
                float v = ps[s][p];
                v += __shfl_xor_sync(0xffffffffu, v, 1);
                v += __shfl_xor_sync(0xffffffffu, v, 2);
                ps[s][p] = v;
            }
        if ((lane & 3) == 0) {
            #pragma unroll
            for (int f = 0; f < 2; f++)
                #pragma unroll
                for (int rr = 0; rr < 2; rr++) {
                    int el = (mw * 2 + f) * 16 + (lane >> 2) + rr * 8;
                    #pragma unroll
                    for (int p = 0; p < 3; p++)
                        red[(nw * 3 + p) * TILE_E + el] += ps[f * 2 + rr][p];
                }
        }
    }
    __syncthreads();

    if (tid < TILE_E && Sge[tid] >= 0) {
        float s0 = 0.f, s1 = 0.f, s2 = 0.f;
        #pragma unroll
        for (int w = 0; w < NWARP_N; w++) {
            s0 += red[(w * 3 + 0) * TILE_E + tid];
            s1 += red[(w * 3 + 1) * TILE_E + tid];
            s2 += red[(w * 3 + 2) * TILE_E + tid];
        }
        float res;
        if (FULL) {
            float p0 = pw[0], p1 = pw[1], p2 = pw[2];
            float mx = fmaxf(p0, fmaxf(p1, p2));
            float e0 = expf(p0 - mx), e1 = expf(p1 - mx), e2 = expf(p2 - mx);
            float inv = 1.f / (e0 + e1 + e2);
            float ss = s0 + sb2[0];
            float sc = s1 + cb2[0];
            float sm = s2 + mb2[0];
            res = (e0 * ss + e1 * sc + e2 * sm) * inv;
        } else {
            res = s0 + sb2[0];
        }
        out[Sge[tid]] = res;
    }
}

extern "C" void kernel_launch(void* const* d_in, const int* in_sizes, int n_in,
                              void* d_out, int out_size)
{
    const float* z    = (const float*)d_in[0];
    const float* chem = (const float*)d_in[1];
    const int*   edge = (const int*)d_in[2];
    const int*   mask = (const int*)d_in[3];
    const float* sw1  = (const float*)d_in[4];
    const float* sb1  = (const float*)d_in[5];
    const float* sw2  = (const float*)d_in[6];
    const float* sb2  = (const float*)d_in[7];
    const float* cw1  = (const float*)d_in[8];
    const float* cb1  = (const float*)d_in[9];
    const float* cw2  = (const float*)d_in[10];
    const float* cb2  = (const float*)d_in[11];
    const float* mw1  = (const float*)d_in[12];
    const float* mb1  = (const float*)d_in[13];
    const float* mw2  = (const float*)d_in[14];
    const float* mb2  = (const float*)d_in[15];
    const float* pw   = (const float*)d_in[16];
    float*       out  = (float*)d_out;

    const int E = in_sizes[2] / 2;

    zero_kernel<<<1, 1>>>();
    compact_kernel<<<(E + 511) / 512, 512>>>(edge, mask, E);
    {
        int total = KTOT * HTOT + HTOT;
        pack_kernel<<<(total + 255) / 256, 256>>>(sw1, sb1, sw2,
                                                  cw1, cb1, cw2,
                                                  mw1, mb1, mw2);
    }

    cudaFuncSetAttribute(decoder_kernel<true>,
                         cudaFuncAttributeMaxDynamicSharedMemorySize, SM_TOTAL);
    cudaFuncSetAttribute(decoder_kernel<false>,
                         cudaFuncAttributeMaxDynamicSharedMemorySize, SM_TOTAL);

    const int nblocks = (E + TILE_E - 1) / TILE_E;
    decoder_kernel<true><<<nblocks, THREADS, SM_TOTAL>>>(
        z, chem, edge, sb2, cb2, mb2, pw, out);
    decoder_kernel<false><<<nblocks, THREADS, SM_TOTAL>>>(
        z, chem, edge, sb2, cb2, mb2, pw, out);
}